// round 2
// baseline (speedup 1.0000x reference)
#include <cuda_runtime.h>
#include <math.h>

#define BB 256
#define LL 256
#define VV 14
#define EMBD 512
#define HH 128
#define OC 256
#define NP 196          // 14*14 token pairs
#define KLIN 32768      // OC*HH
#define NJ 128
#define SPLITK 64
#define KC (KLIN/SPLITK)  // 512

// ---------------- scratch (static device allocations; no cudaMalloc) -------
__device__ float g_poolT_e[EMBD*NP];
__device__ float g_poolT_f[EMBD*NP];
__device__ float g_P2_e[3*OC*NP];
__device__ float g_P2_f[3*OC*NP];
__device__ int   g_pairIdx[BB*HH];
__device__ float g_conv[BB*KLIN];          // 33.5 MB, reused enemy->friend
__device__ float g_partial[SPLITK*BB*NJ];  // 8 MB split-K partials
__device__ float g_vec[BB*NJ];             // logits / enemy_out / f1, reused
__device__ float g_r[3*BB*64];
__device__ float g_Wsum[3*64*128];
__device__ float g_Lmid[64*256];
__device__ int   g_tok[BB*256];

// ---------------- pair-pooled embedding LUT: poolT[c][p] -------------------
__global__ void k_poolT(int which, const float* __restrict__ emb){
    int idx = blockIdx.x*blockDim.x + threadIdx.x;
    if (idx >= EMBD*NP) return;
    int p = idx % NP;
    int c = idx / NP;
    int t1 = p / VV, t2 = p % VV;
    float v = fmaxf(emb[t1*EMBD + c], emb[t2*EMBD + c]);
    (which ? g_poolT_f : g_poolT_e)[idx] = v;
}

// ---------------- P2[kh][o][p] = sum_c poolT[c][p] * w[o,c,kh,1] -----------
__global__ void k_pbuild(int which, const float* __restrict__ cw){
    int o = blockIdx.x;         // 0..255
    int p = threadIdx.x;        // 0..195
    const float* poolT = which ? g_poolT_f : g_poolT_e;
    float*       P2    = which ? g_P2_f    : g_P2_e;
    const float* wo = cw + (size_t)o*EMBD*9;   // [i][kh][kw], kw=1 only
    float a0=0.f, a1=0.f, a2=0.f;
    for (int c=0; c<EMBD; c++){
        float v = poolT[c*NP + p];
        a0 = fmaf(v, wo[c*9+1], a0);   // kh=0, kw=1
        a1 = fmaf(v, wo[c*9+4], a1);   // kh=1
        a2 = fmaf(v, wo[c*9+7], a2);   // kh=2
    }
    P2[(0*OC + o)*NP + p] = a0;
    P2[(1*OC + o)*NP + p] = a1;
    P2[(2*OC + o)*NP + p] = a2;
}

// ---------------- pair index per pooled position ---------------------------
__global__ void k_pairidx(int which, const int* __restrict__ x){
    int idx = blockIdx.x*blockDim.x + threadIdx.x;
    if (idx >= BB*HH) return;
    const int* tok = which ? g_tok : x;
    int b = idx / HH, h = idx % HH;
    g_pairIdx[idx] = tok[b*LL + 2*h]*VV + tok[b*LL + 2*h + 1];
}

// ---------------- conv via LUT gather: conv[b][o*128+h] --------------------
__global__ void k_conv(int which, const float* __restrict__ bias){
    int idx = blockIdx.x*256 + threadIdx.x;     // < BB*KLIN
    const float* P2 = which ? g_P2_f : g_P2_e;
    int h = idx & 127;
    int o = (idx >> 7) & 255;
    int b = idx >> 15;
    const int* pi = g_pairIdx + b*HH;
    float v = bias[o];
    if (h > 0)   v += P2[(0*OC + o)*NP + pi[h-1]];
    v += P2[(1*OC + o)*NP + pi[h]];
    if (h < 127) v += P2[(2*OC + o)*NP + pi[h+1]];
    g_conv[idx] = v;
}

// ---------------- f32x2 helpers -------------------------------------------
__device__ __forceinline__ unsigned long long pk2(float lo, float hi){
    unsigned long long r;
    asm("mov.b64 %0, {%1, %2};" : "=l"(r) : "f"(lo), "f"(hi));
    return r;
}
__device__ __forceinline__ void upk2(unsigned long long v, float& lo, float& hi){
    asm("mov.b64 {%0, %1}, %2;" : "=f"(lo), "=f"(hi) : "l"(v));
}
__device__ __forceinline__ void ffma2(unsigned long long& c, unsigned long long a, unsigned long long b){
    asm("fma.rn.f32x2 %0, %1, %2, %0;" : "+l"(c) : "l"(a), "l"(b));
}

// ---------------- split-K GEMM: [256 x 32768] * [32768 x 128] --------------
// grid (2, SPLITK), block 256. Tile 128(M) x 128(N), K-chunk 512.
__global__ __launch_bounds__(256) void k_gemm(const float* __restrict__ W){
    __shared__ float As[16][128];
    __shared__ float Bs[16][128];
    const float* A = g_conv;
    int tid = threadIdx.x;
    int m0 = blockIdx.x * 128;
    int k0 = blockIdx.y * KC;
    int tx = tid & 15, ty = tid >> 4;       // 16x16 thread grid: 8 cols x 8 rows each
    int lk = tid & 15, lm = tid >> 4;       // A loader
    int bj = tid & 127, bk = tid >> 7;      // B loader
    unsigned long long acc[4][8];
    #pragma unroll
    for (int i=0;i<4;i++)
        #pragma unroll
        for (int j=0;j<8;j++) acc[i][j] = 0ull;

    for (int t = 0; t < KC; t += 16){
        #pragma unroll
        for (int i=0;i<8;i++)
            As[lk][lm + i*16] = A[(size_t)(m0 + lm + i*16)*KLIN + k0 + t + lk];
        #pragma unroll
        for (int i=0;i<8;i++)
            Bs[bk + i*2][bj] = W[(size_t)(k0 + t + bk + i*2)*NJ + bj];
        __syncthreads();
        #pragma unroll
        for (int kk=0; kk<16; kk++){
            float4 a0 = *(const float4*)&As[kk][ty*8];
            float4 a1 = *(const float4*)&As[kk][ty*8 + 4];
            float4 b0 = *(const float4*)&Bs[kk][tx*4];
            float4 b1 = *(const float4*)&Bs[kk][64 + tx*4];
            unsigned long long ap[4] = { pk2(a0.x,a0.y), pk2(a0.z,a0.w),
                                         pk2(a1.x,a1.y), pk2(a1.z,a1.w) };
            unsigned long long bd[8] = { pk2(b0.x,b0.x), pk2(b0.y,b0.y),
                                         pk2(b0.z,b0.z), pk2(b0.w,b0.w),
                                         pk2(b1.x,b1.x), pk2(b1.y,b1.y),
                                         pk2(b1.z,b1.z), pk2(b1.w,b1.w) };
            #pragma unroll
            for (int i=0;i<4;i++)
                #pragma unroll
                for (int j=0;j<8;j++)
                    ffma2(acc[i][j], ap[i], bd[j]);
        }
        __syncthreads();
    }
    float* outp = g_partial + (size_t)blockIdx.y * (BB*NJ);
    #pragma unroll
    for (int i=0;i<4;i++){
        int mlo = m0 + ty*8 + 2*i;
        float rlo[8], rhi[8];
        #pragma unroll
        for (int j=0;j<8;j++) upk2(acc[i][j], rlo[j], rhi[j]);
        *(float4*)&outp[(size_t)mlo*NJ + tx*4]          = make_float4(rlo[0],rlo[1],rlo[2],rlo[3]);
        *(float4*)&outp[(size_t)mlo*NJ + 64 + tx*4]     = make_float4(rlo[4],rlo[5],rlo[6],rlo[7]);
        *(float4*)&outp[(size_t)(mlo+1)*NJ + tx*4]      = make_float4(rhi[0],rhi[1],rhi[2],rhi[3]);
        *(float4*)&outp[(size_t)(mlo+1)*NJ + 64 + tx*4] = make_float4(rhi[4],rhi[5],rhi[6],rhi[7]);
    }
}

// ---------------- deterministic split-K reduce + bias ----------------------
__global__ void k_reduce(const float* __restrict__ bias){
    int idx = blockIdx.x*256 + threadIdx.x;     // < BB*NJ
    float s = bias[idx & 127];
    #pragma unroll 8
    for (int kz=0; kz<SPLITK; kz++) s += g_partial[(size_t)kz*(BB*NJ) + idx];
    g_vec[idx] = s;
}

// ---------------- softmax over 128 (enemy) ---------------------------------
__global__ void k_softmax128(){
    __shared__ float red[128];
    int b = blockIdx.x, t = threadIdx.x;
    float v = g_vec[b*128 + t];
    red[t] = v; __syncthreads();
    for (int s=64; s; s>>=1){ if (t < s) red[t] = fmaxf(red[t], red[t+s]); __syncthreads(); }
    float mx = red[0]; __syncthreads();
    float e = expf(v - mx);
    red[t] = e; __syncthreads();
    for (int s=64; s; s>>=1){ if (t < s) red[t] += red[t+s]; __syncthreads(); }
    g_vec[b*128 + t] = e / red[0];
}

// ---------------- manipulator: collapsed conv weights ----------------------
// variant 0: h=0 edge (kh=1,2)  variant 1: interior (kh=0,1,2)  variant 2: h=127 (kh=0,1)
__global__ void k_wsum(const float* __restrict__ mcw){
    int idx = blockIdx.x*256 + threadIdx.x;     // < 3*64*128
    if (idx >= 3*64*128) return;
    int v = idx / 8192;
    int rem = idx % 8192;           // o*128+c
    int base = rem*9 + 1;
    float w0 = mcw[base], w1 = mcw[base+3], w2 = mcw[base+6];
    g_Wsum[idx] = (v==0) ? (w1+w2) : (v==1) ? (w0+w1+w2) : (w0+w1);
}

__global__ void k_rgemm(const float* __restrict__ mcb){
    int idx = blockIdx.x*256 + threadIdx.x;     // < 3*BB*64
    if (idx >= 3*BB*64) return;
    int v = idx / (BB*64);
    int rem = idx % (BB*64);
    int b = rem / 64, o = rem % 64;
    const float* eo = g_vec + b*128;
    const float* ws = g_Wsum + v*8192 + o*128;
    float s = mcb[o];
    for (int c=0;c<128;c++) s = fmaf(eo[c], ws[c], s);
    g_r[idx] = fmaxf(s, 0.f);
}

__global__ void k_lmid(const float* __restrict__ mlw){
    int idx = blockIdx.x*256 + threadIdx.x;     // < 64*256
    if (idx >= 64*256) return;
    int o = idx >> 8, j = idx & 255;
    float s = 0.f;
    for (int h=1; h<127; h++) s += mlw[(size_t)(o*128 + h)*256 + j];
    g_Lmid[idx] = s;
}

__global__ void k_mtok(const float* __restrict__ mlw, const float* __restrict__ mlb){
    int idx = blockIdx.x*256 + threadIdx.x;     // < BB*256
    if (idx >= BB*256) return;
    int b = idx >> 8, j = idx & 255;
    const float* r0   = g_r + 0*BB*64 + b*64;
    const float* ri   = g_r + 1*BB*64 + b*64;
    const float* r127 = g_r + 2*BB*64 + b*64;
    float s = mlb[j];
    for (int o=0; o<64; o++){
        s = fmaf(r0[o],   mlw[(size_t)o*32768 + j],          s);
        s = fmaf(ri[o],   g_Lmid[o*256 + j],                 s);
        s = fmaf(r127[o], mlw[(size_t)o*32768 + 32512 + j],  s);
    }
    int t = (int)floorf(fabsf(s) * 100.0f);
    g_tok[idx] = t % VV;
}

// ---------------- final linear (128->14) + softmax -------------------------
__global__ void k_lin2sm(const float* __restrict__ w2, const float* __restrict__ b2,
                         float* __restrict__ out){
    int b = blockIdx.x, v = threadIdx.x;  // 32 threads
    float logit = 0.f;
    if (v < VV){
        logit = b2[v];
        const float* f = g_vec + b*128;
        for (int j=0;j<128;j++) logit = fmaf(f[j], w2[j*VV + v], logit);
    }
    float mx = (v < VV) ? logit : -INFINITY;
    for (int off=16; off; off>>=1) mx = fmaxf(mx, __shfl_xor_sync(0xffffffffu, mx, off));
    float e = (v < VV) ? expf(logit - mx) : 0.f;
    float s = e;
    for (int off=16; off; off>>=1) s += __shfl_xor_sync(0xffffffffu, s, off);
    if (v < VV) out[b*VV + v] = e / s;
}

// ---------------- launch ----------------------------------------------------
extern "C" void kernel_launch(void* const* d_in, const int* in_sizes, int n_in,
                              void* d_out, int out_size){
    const int*   x    = (const int*)  d_in[0];
    const float* eemb = (const float*)d_in[1];
    const float* ecw  = (const float*)d_in[2];
    const float* ecb  = (const float*)d_in[3];
    const float* elw  = (const float*)d_in[4];
    const float* elb  = (const float*)d_in[5];
    // d_in[6] rand_proj: dead (fog_of_war is the identity permutation)
    const float* mcw  = (const float*)d_in[7];
    const float* mcb  = (const float*)d_in[8];
    const float* mlw  = (const float*)d_in[9];
    const float* mlb  = (const float*)d_in[10];
    const float* femb = (const float*)d_in[11];
    const float* fcw  = (const float*)d_in[12];
    const float* fcb  = (const float*)d_in[13];
    const float* flw1 = (const float*)d_in[14];
    const float* flb1 = (const float*)d_in[15];
    const float* flw2 = (const float*)d_in[16];
    const float* flb2 = (const float*)d_in[17];
    float* out = (float*)d_out;

    // LUT builds (token-independent) for both branches up front
    k_poolT<<<(EMBD*NP+255)/256, 256>>>(0, eemb);
    k_poolT<<<(EMBD*NP+255)/256, 256>>>(1, femb);
    k_pbuild<<<OC, NP>>>(0, ecw);
    k_pbuild<<<OC, NP>>>(1, fcw);

    // enemy branch
    k_pairidx<<<(BB*HH+255)/256, 256>>>(0, x);
    k_conv<<<(BB*KLIN)/256, 256>>>(0, ecb);
    k_gemm<<<dim3(2, SPLITK), 256>>>(elw);
    k_reduce<<<(BB*NJ)/256, 256>>>(elb);
    k_softmax128<<<BB, 128>>>();

    // manipulator (collapsed) -> tokens
    k_wsum<<<(3*64*128+255)/256, 256>>>(mcw);
    k_rgemm<<<(3*BB*64+255)/256, 256>>>(mcb);
    k_lmid<<<(64*256+255)/256, 256>>>(mlw);
    k_mtok<<<(BB*256+255)/256, 256>>>(mlw, mlb);

    // friend branch
    k_pairidx<<<(BB*HH+255)/256, 256>>>(1, x);
    k_conv<<<(BB*KLIN)/256, 256>>>(1, fcb);
    k_gemm<<<dim3(2, SPLITK), 256>>>(flw1);
    k_reduce<<<(BB*NJ)/256, 256>>>(flb1);
    k_lin2sm<<<BB, 32>>>(flw2, flb2, out);
}